// round 7
// baseline (speedup 1.0000x reference)
#include <cuda_runtime.h>

#define BB 2048
#define TT 1024
#define DD 64
#define HH 16
#define NW 8               // warps per K1 block
#define CH 128             // timesteps per K1 warp
#define INV_TAU (1.0f/6.0f)

typedef unsigned long long u64;

// xw scratch: [B, T, 16]
__device__ float g_xw[(size_t)BB * TT * HH];

__device__ __forceinline__ u64 pk2(float lo, float hi) {
    u64 r; asm("mov.b64 %0, {%1,%2};" : "=l"(r) : "f"(lo), "f"(hi)); return r;
}
__device__ __forceinline__ u64 mul2(u64 a, u64 b) {
    u64 r; asm("mul.rn.f32x2 %0, %1, %2;" : "=l"(r) : "l"(a), "l"(b)); return r;
}
__device__ __forceinline__ u64 fma2(u64 a, u64 b, u64 c) {
    u64 r; asm("fma.rn.f32x2 %0, %1, %2, %3;" : "=l"(r) : "l"(a), "l"(b), "l"(c)); return r;
}
__device__ __forceinline__ u64 add2(u64 a, u64 b) {
    u64 r; asm("add.rn.f32x2 %0, %1, %2;" : "=l"(r) : "l"(a), "l"(b)); return r;
}
__device__ __forceinline__ float hadd2(u64 a) {
    float lo, hi; asm("mov.b64 {%0,%1}, %2;" : "=f"(lo), "=f"(hi) : "l"(a)); return lo + hi;
}

// exp(-k) for k in [1/6, 2/3): degree-5 poly about c=5/12. rel err ~4e-7.
__device__ __forceinline__ float expnk(float k) {
    const float E = 0.6592406302004438f;         // exp(-5/12)
    float x = k - 0.4166666666666667f;
    float p = -E / 120.0f;
    p = fmaf(p, x,  E / 24.0f);
    p = fmaf(p, x, -E / 6.0f);
    p = fmaf(p, x,  E * 0.5f);
    p = fmaf(p, x, -E);
    p = fmaf(p, x,  E);
    return p;
}

// ============================================================================
// K1: synaptic chunk-scan + x_cat + input projection -> g_xw
// Block = 256 threads (8 warps) = one batch. Warp w owns t in [128w, 128w+128).
// Lane owns d-pair (2l, 2l+1). Projection: h-packed f32x2 accumulators; all-u64
// butterfly; lanes 0-7 end holding xw h-pair P(l) and store one STG.64.
// ============================================================================
__global__ void __launch_bounds__(256, 2) k1_syn_proj(
    const float* __restrict__ inputs,   // [B,T,64]
    const float* __restrict__ syn_x0,   // [B,64]
    const float* __restrict__ w_ih,     // [128,16]
    float* __restrict__ out_xcat)       // [B,T,128]
{
    __shared__ float wsm[2*DD][HH];     // raw copy of w_ih
    __shared__ float Asm[NW][DD];
    __shared__ float Bsm[NW][DD];
    __shared__ float Ssm[NW][DD];

    const int b    = blockIdx.x;
    const int tid  = threadIdx.x;
    const int w    = tid >> 5;
    const int lane = tid & 31;
    const int t0   = w * CH;

    // ---- stage weights to smem (coalesced float4) ----
    {
        const float4* src = reinterpret_cast<const float4*>(w_ih);
        float4* dst = reinterpret_cast<float4*>(&wsm[0][0]);
        for (int i = tid; i < 2*DD*HH/4; i += 256) dst[i] = src[i];
    }
    __syncthreads();

    // ---- register-stationary weights, h-packed u64 pairs ----
    u64 wa0[8], wa1[8], wb0[8], wb1[8];
#pragma unroll
    for (int i = 0; i < 8; i++) {
        wa0[i] = *reinterpret_cast<const u64*>(&wsm[2*lane   ][2*i]);
        wa1[i] = *reinterpret_cast<const u64*>(&wsm[2*lane+1 ][2*i]);
        wb0[i] = *reinterpret_cast<const u64*>(&wsm[64+2*lane][2*i]);
        wb1[i] = *reinterpret_cast<const u64*>(&wsm[65+2*lane][2*i]);
    }

    const float2* ip = reinterpret_cast<const float2*>(inputs)
                       + ((size_t)b*TT + t0)*(DD/2) + lane;

    // ---- phase 1: compose chunk affine (A,B) per owned d ----
    {
        float2 A  = make_float2(1.f, 1.f);
        float2 Bc = make_float2(0.f, 0.f);
        float2 buf[4];
#pragma unroll
        for (int k = 0; k < 4; k++) buf[k] = ip[k*(DD/2)];
#pragma unroll 2
        for (int t = 0; t < CH; t++) {
            float2 in = buf[t & 3];
            if (t + 4 < CH) buf[t & 3] = ip[(t + 4)*(DD/2)];
            float kx = fmaf(0.5f, in.x, INV_TAU);
            float ky = fmaf(0.5f, in.y, INV_TAU);
            float ex = expnk(kx);
            float ey = expnk(ky);
            float rx = __fdividef(INV_TAU, kx);
            float ry = __fdividef(INV_TAU, ky);
            float bx = fmaf(-rx, ex, rx);      // r(1-e)
            float by = fmaf(-ry, ey, ry);
            A.x *= ex;  A.y *= ey;
            Bc.x = fmaf(ex, Bc.x, bx);
            Bc.y = fmaf(ey, Bc.y, by);
        }
        *reinterpret_cast<float2*>(&Asm[w][2*lane]) = A;
        *reinterpret_cast<float2*>(&Bsm[w][2*lane]) = Bc;
    }
    __syncthreads();

    // ---- phase 2: exclusive block scan over 8 chunks, per d ----
    if (tid < DD) {
        float s = syn_x0[b*DD + tid];
#pragma unroll
        for (int c = 0; c < NW; c++) {
            Ssm[c][tid] = s;
            s = fmaf(Asm[c][tid], s, Bsm[c][tid]);
        }
    }
    __syncthreads();

    // ---- phase 3: re-stream inputs (L2 hits), emit x_cat + xw ----
    float2 s = *reinterpret_cast<float2*>(&Ssm[w][2*lane]);
    float2* xc = reinterpret_cast<float2*>(out_xcat)
                 + ((size_t)b*TT + t0)*DD + lane;
    float* xwp = g_xw + ((size_t)b*TT + t0)*HH;
    // h-pair index this lane owns after the u64 butterfly (lanes 0-7 store)
    const int P = ((lane & 1) << 2) | (lane & 2) | ((lane & 4) >> 2);

    float2 buf[4];
#pragma unroll
    for (int k = 0; k < 4; k++) buf[k] = ip[k*(DD/2)];

#pragma unroll 2
    for (int t = 0; t < CH; t++) {
        float2 in = buf[t & 3];
        if (t + 4 < CH) buf[t & 3] = ip[(t + 4)*(DD/2)];

        float kx = fmaf(0.5f, in.x, INV_TAU);
        float ky = fmaf(0.5f, in.y, INV_TAU);
        float ex = expnk(kx);
        float ey = expnk(ky);
        float rx = __fdividef(INV_TAU, kx);
        float ry = __fdividef(INV_TAU, ky);

        float2 sx;                       // syn(pre-update) * input
        sx.x = s.x * in.x;
        sx.y = s.y * in.y;

        xc[t*DD]      = in;              // x_cat[:, :64]
        xc[t*DD + 32] = sx;              // x_cat[:, 64:]

        float bx = fmaf(-rx, ex, rx);
        float by = fmaf(-ry, ey, ry);
        s.x = fmaf(ex, s.x, bx);
        s.y = fmaf(ey, s.y, by);

        // ---- h-packed projection: acc[i] = (xw[2i], xw[2i+1]) partials ----
        u64 dx0 = pk2(in.x, in.x);
        u64 dx1 = pk2(in.y, in.y);
        u64 ds0 = pk2(sx.x, sx.x);
        u64 ds1 = pk2(sx.y, sx.y);
        u64 acc[8];
#pragma unroll
        for (int i = 0; i < 8; i++) {
            u64 a = mul2(dx0, wa0[i]);
            a = fma2(dx1, wa1[i], a);
            a = fma2(ds0, wb0[i], a);
            a = fma2(ds1, wb1[i], a);
            acc[i] = a;
        }

        // ---- all-u64 butterfly: halve array (xor1,2,4), fold (xor8,16) ----
        u64 q4[4];
        {
            bool lo = (lane & 1) == 0;
#pragma unroll
            for (int i = 0; i < 4; i++) {
                u64 send = lo ? acc[4 + i] : acc[i];
                u64 recv = __shfl_xor_sync(0xffffffffu, send, 1);
                q4[i] = add2(lo ? acc[i] : acc[4 + i], recv);
            }
        }
        u64 q2[2];
        {
            bool lo = (lane & 2) == 0;
#pragma unroll
            for (int i = 0; i < 2; i++) {
                u64 send = lo ? q4[2 + i] : q4[i];
                u64 recv = __shfl_xor_sync(0xffffffffu, send, 2);
                q2[i] = add2(lo ? q4[i] : q4[2 + i], recv);
            }
        }
        u64 q1;
        {
            bool lo = (lane & 4) == 0;
            u64 send = lo ? q2[1] : q2[0];
            u64 recv = __shfl_xor_sync(0xffffffffu, send, 4);
            q1 = add2(lo ? q2[0] : q2[1], recv);
        }
        q1 = add2(q1, __shfl_xor_sync(0xffffffffu, q1, 8));
        q1 = add2(q1, __shfl_xor_sync(0xffffffffu, q1, 16));

        // lanes 0-7 store their complete xw h-pair (coalesced 64B)
        if (lane < 8)
            *reinterpret_cast<u64*>(&xwp[t*HH + 2*P]) = q1;
    }
}

// ============================================================================
// K2: sequential ReLU RNN + hidden + linear output. One warp per batch.
// Shuffle-free: h vector lives in smem; LDS.128 broadcast + packed f32x2 math.
// Output dot computed one step deferred (from the h loaded this iteration).
// ============================================================================
__global__ void __launch_bounds__(32) k2_rnn(
    const float* __restrict__ h0,       // [B,16]
    const float* __restrict__ w_hh,     // [16,16]
    const float* __restrict__ bias,     // [16]
    const float* __restrict__ lin_w,    // [16]
    const float* __restrict__ lin_b,    // [1]
    float* __restrict__ out_output,     // [B,T]
    float* __restrict__ out_hidden)     // [B,T,16]
{
    __shared__ float hsm[HH];

    const int lane = threadIdx.x;
    const int b    = blockIdx.x;
    const int j    = lane & 15;

    // column j of W_hh, packed over i-pairs
    u64 wc[8], lwp[8];
#pragma unroll
    for (int k = 0; k < 8; k++) {
        wc[k]  = pk2(w_hh[(2*k)*HH + j], w_hh[(2*k+1)*HH + j]);
        lwp[k] = pk2(lin_w[2*k], lin_w[2*k+1]);
    }
    const float biasj = bias[j];
    const float lb    = lin_b[0];

    if (lane < HH) hsm[j] = h0[b*HH + j];
    __syncwarp();

    const float* xp = g_xw + (size_t)b*TT*HH + j;
    float*      hid = out_hidden + (size_t)b*TT*HH;
    float*       op = out_output + (size_t)b*TT;

    float buf[8];
#pragma unroll
    for (int p = 0; p < 8; p++) buf[p] = xp[p*HH];

    for (int t = 0; t < TT; t++) {
        float xwv = buf[t & 7];
        if (t + 8 < TT) buf[t & 7] = xp[(t + 8)*HH];

        // load full h (state after step t-1): 4x LDS.128 broadcast
        float4 h4a = *reinterpret_cast<const float4*>(&hsm[0]);
        float4 h4b = *reinterpret_cast<const float4*>(&hsm[4]);
        float4 h4c = *reinterpret_cast<const float4*>(&hsm[8]);
        float4 h4d = *reinterpret_cast<const float4*>(&hsm[12]);
        u64 H[8];
        H[0] = pk2(h4a.x, h4a.y); H[1] = pk2(h4a.z, h4a.w);
        H[2] = pk2(h4b.x, h4b.y); H[3] = pk2(h4b.z, h4b.w);
        H[4] = pk2(h4c.x, h4c.y); H[5] = pk2(h4c.z, h4c.w);
        H[6] = pk2(h4d.x, h4d.y); H[7] = pk2(h4d.z, h4d.w);

        // matvec for column j: 8 fma2 in two chains
        u64 a0 = pk2(xwv + biasj, 0.0f);
        u64 a1 = pk2(0.0f, 0.0f);
#pragma unroll
        for (int k = 0; k < 8; k += 2) {
            a0 = fma2(H[k],     wc[k],     a0);
            a1 = fma2(H[k + 1], wc[k + 1], a1);
        }
        float hj = fmaxf(hadd2(add2(a0, a1)), 0.0f);

        if (lane < HH) hid[t*HH + j] = hj;

        // output for step t-1 from H (every lane computes; lane 0 stores)
        u64 v0 = pk2(0.0f, 0.0f), v1 = pk2(0.0f, 0.0f);
#pragma unroll
        for (int k = 0; k < 8; k += 2) {
            v0 = fma2(H[k],     lwp[k],     v0);
            v1 = fma2(H[k + 1], lwp[k + 1], v1);
        }
        if (lane == 0 && t > 0) op[t - 1] = hadd2(add2(v0, v1)) + lb;

        if (lane < HH) hsm[j] = hj;
        __syncwarp();
    }

    // epilogue: output for t = TT-1
    {
        float4 h4a = *reinterpret_cast<const float4*>(&hsm[0]);
        float4 h4b = *reinterpret_cast<const float4*>(&hsm[4]);
        float4 h4c = *reinterpret_cast<const float4*>(&hsm[8]);
        float4 h4d = *reinterpret_cast<const float4*>(&hsm[12]);
        u64 v0 = pk2(0.f, 0.f), v1 = pk2(0.f, 0.f);
        u64 H[8];
        H[0] = pk2(h4a.x, h4a.y); H[1] = pk2(h4a.z, h4a.w);
        H[2] = pk2(h4b.x, h4b.y); H[3] = pk2(h4b.z, h4b.w);
        H[4] = pk2(h4c.x, h4c.y); H[5] = pk2(h4c.z, h4c.w);
        H[6] = pk2(h4d.x, h4d.y); H[7] = pk2(h4d.z, h4d.w);
#pragma unroll
        for (int k = 0; k < 8; k += 2) {
            v0 = fma2(H[k],     lwp[k],     v0);
            v1 = fma2(H[k + 1], lwp[k + 1], v1);
        }
        if (lane == 0) op[TT - 1] = hadd2(add2(v0, v1)) + lb;
    }
}

extern "C" void kernel_launch(void* const* d_in, const int* in_sizes, int n_in,
                              void* d_out, int out_size) {
    const float* inputs = (const float*)d_in[0];   // [B,T,64]
    const float* syn_x0 = (const float*)d_in[1];   // [B,64]
    const float* h0     = (const float*)d_in[2];   // [B,16]
    const float* w_ih   = (const float*)d_in[3];   // [128,16]
    const float* w_hh   = (const float*)d_in[4];   // [16,16]
    const float* bias   = (const float*)d_in[5];   // [16]
    const float* lin_w  = (const float*)d_in[6];   // [16,1]
    const float* lin_b  = (const float*)d_in[7];   // [1]

    float* out = (float*)d_out;
    // tuple concat order: output [B,T,1], hidden [B,T,16], x_cat [B,T,128]
    float* out_output = out;
    float* out_hidden = out + (size_t)BB*TT;
    float* out_xcat   = out + (size_t)BB*TT + (size_t)BB*TT*HH;

    k1_syn_proj<<<BB, 256>>>(inputs, syn_x0, w_ih, out_xcat);
    k2_rnn<<<BB, 32>>>(h0, w_hh, bias, lin_w, lin_b, out_output, out_hidden);
}